// round 2
// baseline (speedup 1.0000x reference)
#include <cuda_runtime.h>
#include <stdint.h>

#define HWC    (512*512)
#define NCH    64
#define NSEG   256
#define NB     4
#define CG     32          // channels per block
#define NCG    2           // channel groups
#define CHUNK  4096        // pixels per block
#define NCHUNK 64          // HWC / CHUNK
#define TILE   128         // pixels per staged tile
#define NT     (CHUNK/TILE)
#define TSTR   129         // tile row stride (odd -> conflict-free transposed reads)
#define TPB    256

// Per-block partial tables: [B][NCG][NCHUNK][CG][NSEG] encoded u32 (16.8 MB)
__device__ unsigned g_scratch[(size_t)NB * NCG * NCHUNK * CG * NSEG];

// smem layout (dynamic):
//   unsigned tile[CG][TSTR]   16512 B   (encoded feature values)
//   unsigned smax[CG][257]    32896 B   (stride 257 -> conflict-free atomics)
//   uint8    slab[CHUNK]       4096 B
#define SMEM_BYTES ((CG*TSTR + CG*257)*4 + CHUNK)

// Monotone float->uint encoding: order-preserving, enc(x) >= 1 for all
// finite/inf floats, so 0 is the identity/empty sentinel for max.
__device__ __forceinline__ unsigned enc_f32(float f) {
    unsigned b = __float_as_uint(f);
    return b ^ ((unsigned)((int)b >> 31) | 0x80000000u);
}

__global__ void __launch_bounds__(TPB, 4) seg_kernel(
    const float* __restrict__ feats,   // [B, C, 512, 512]
    const int*   __restrict__ labels)  // [B, 1, 512, 512]
{
    extern __shared__ unsigned char sm_raw[];
    unsigned*      tilebuf = (unsigned*)sm_raw;                       // [CG][TSTR]
    unsigned*      smax    = (unsigned*)(sm_raw + CG*TSTR*4);         // [CG][257]
    unsigned char* slab    = (unsigned char*)(sm_raw + (CG*TSTR + CG*257)*4);

    const int tid  = threadIdx.x;
    const int lane = tid & 31;
    const int w    = tid >> 5;            // warp id (0..7)
    const int chunk = blockIdx.x;
    const int cg    = blockIdx.y;
    const int b     = blockIdx.z;
    const int base  = chunk * CHUNK;      // plane-linear pixel base

    // Init private table
    for (int i = tid; i < CG * 257; i += TPB) smax[i] = 0u;

    // Labels -> uint8 smem (values 0..255)
    {
        const int* lb = labels + (size_t)b * HWC + base;
        for (int i = tid; i < CHUNK; i += TPB) slab[i] = (unsigned char)lb[i];
    }

    const float* fbase = feats + (size_t)(b * NCH + cg * CG) * HWC + base;

    // Register-staged tile: warp w owns channels 4w..4w+3; lane-stride-1 pixels
    // (px = lane + 32k) -> coalesced LDG.32 and conflict-free STS.32.
    float r[16];
    #pragma unroll
    for (int j = 0; j < 4; j++) {
        const float* fc = fbase + (size_t)(4*w + j) * HWC;
        #pragma unroll
        for (int k = 0; k < 4; k++) r[j*4 + k] = fc[lane + 32*k];
    }

    for (int t = 0; t < NT; t++) {
        // --- STS phase: encode + border-mask current tile into smem ---
        {
            const int tb    = base + t * TILE;   // tile is within one image row
            const int row   = tb >> 9;
            const bool ybad = (row == 0) | (row == 511);
            const int xbase = tb & 511;
            #pragma unroll
            for (int j = 0; j < 4; j++) {
                #pragma unroll
                for (int k = 0; k < 4; k++) {
                    int px = lane + 32*k;
                    int x  = xbase + px;         // no carry: xbase%128==0, px<128
                    bool bad = ybad | (x == 0) | (x == 511);
                    unsigned e = bad ? 0u : enc_f32(r[j*4 + k]);
                    tilebuf[(4*w + j) * TSTR + px] = e;
                }
            }
        }
        __syncthreads();

        // Prefetch next tile into registers (LDG latency hidden by process)
        if (t + 1 < NT) {
            #pragma unroll
            for (int j = 0; j < 4; j++) {
                const float* fc = fbase + (size_t)(4*w + j) * HWC + (t+1) * TILE;
                #pragma unroll
                for (int k = 0; k < 4; k++) r[j*4 + k] = fc[lane + 32*k];
            }
        }

        // --- Process phase: lane = channel, warp w handles 16 pixels ---
        // LDS lane-stride 129 -> conflict-free; ATOMS lane-stride 257 ->
        // conflict-free; label is a 1-byte broadcast.
        {
            unsigned* mrow = smax + lane * 257;
            const unsigned*      trow = tilebuf + lane * TSTR + w * 16;
            const unsigned char* sl   = slab + t * TILE + w * 16;
            #pragma unroll
            for (int i = 0; i < 16; i++) {
                unsigned s = sl[i];
                unsigned u = trow[i];
                atomicMax(&mrow[s], u);
            }
        }
        __syncthreads();
    }

    // Dump private table to scratch (non-atomic, fully coalesced STG)
    unsigned* dst = g_scratch + (size_t)((b * NCG + cg) * NCHUNK + chunk) * (CG * NSEG);
    for (int i = tid; i < CG * NSEG; i += TPB) {
        int c = i >> 8, s = i & 255;
        dst[i] = smax[c * 257 + s];
    }
}

// Reduce 64 chunk-partials per output element, decode, empty->0.
__global__ void reduce_kernel(float* __restrict__ out) {
    int idx = blockIdx.x * blockDim.x + threadIdx.x;   // 0..65535 = [B][C][S]
    int s  = idx & 255;
    int c  = (idx >> 8) & 63;
    int b  = idx >> 14;
    int cg = c >> 5, ci = c & 31;
    const unsigned* src = g_scratch
        + (size_t)((b * NCG + cg) * NCHUNK) * (CG * NSEG) + ci * NSEG + s;
    unsigned m = 0;
    #pragma unroll
    for (int k = 0; k < NCHUNK; k++) m = max(m, src[(size_t)k * CG * NSEG]);
    float r;
    if (m == 0u) {
        r = 0.0f;                                      // untouched segment
    } else {
        unsigned bits = (m & 0x80000000u) ? (m ^ 0x80000000u) : ~m;
        r = __uint_as_float(bits);
    }
    out[idx] = r;
}

extern "C" void kernel_launch(void* const* d_in, const int* in_sizes, int n_in,
                              void* d_out, int out_size) {
    const float* feats  = (const float*)d_in[0];   // [4,64,512,512] f32
    const int*   labels = (const int*)d_in[1];     // [4,1,512,512] i32
    float*       out    = (float*)d_out;           // [4,64,256] f32

    cudaFuncSetAttribute(seg_kernel,
                         cudaFuncAttributeMaxDynamicSharedMemorySize, SMEM_BYTES);

    dim3 grid(NCHUNK, NCG, NB);                    // (64, 2, 4) = 512 blocks
    seg_kernel<<<grid, TPB, SMEM_BYTES>>>(feats, labels);

    reduce_kernel<<<(NB*NCH*NSEG)/256, 256>>>(out);
}